// round 2
// baseline (speedup 1.0000x reference)
#include <cuda_runtime.h>

// Problem constants (StridedSparseAttention: B=4, S=4096, D=512, STRIDE=8)
#define BB 4
#define SS 4096
#define DD 512
#define NK 512          // number of strided keys = S/8
#define KSTRIDE 8

#define SCALE 0.044194173824159216f   // 1/sqrt(512)

// Scratch (device globals — no allocations allowed)
__device__ float g_w[(long)BB * SS * NK];   // unnormalized exp(scores), compact [b][i][c]
__device__ float g_rowsum[BB * SS];

// ---------------------------------------------------------------------------
// Kernel 0: zero the attn_weights region and write the mask region of d_out.
// attn region: B*S*S floats (all zeros; valid entries overwritten later)
// mask region: S*S floats, mask[i][j] = (j%8==0 && j<=i) ? 1 : 0
// ---------------------------------------------------------------------------
__global__ void init_out_kernel(float* __restrict__ attn, float* __restrict__ mask) {
    const long NA = (long)BB * SS * SS / 4;   // attn float4 count
    const long NM = (long)SS * SS / 4;        // mask float4 count
    long t0 = (long)blockIdx.x * blockDim.x + threadIdx.x;
    long stride = (long)gridDim.x * blockDim.x;

    float4 z = make_float4(0.f, 0.f, 0.f, 0.f);
    for (long t = t0; t < NA; t += stride)
        reinterpret_cast<float4*>(attn)[t] = z;

    for (long t = t0; t < NM; t += stride) {
        int i  = (int)(t >> 10);            // (t*4) / 4096
        int j0 = (int)((t & 1023) << 2);    // (t*4) % 4096
        float4 m = z;
        if ((j0 & 7) == 0 && j0 <= i) m.x = 1.0f;  // only e=0 can be %8==0
        reinterpret_cast<float4*>(mask)[t] = m;
    }
}

// ---------------------------------------------------------------------------
// Kernel 1: QK GEMM. scores[i][c] = dot(q[b][i], k[b][8c]) * scale
// writes g_w[b][i][c] = (8c<=i) ? exp(score) : 0
// Tile: M=64 queries, N=64 keys, k-chunk=32.  256 threads, 4x4 microtiles.
// ---------------------------------------------------------------------------
__global__ __launch_bounds__(256) void qk_kernel(
    const float* __restrict__ q, const float* __restrict__ k)
{
    const int b  = blockIdx.z;
    const int mt = blockIdx.y;     // query tile
    const int nt = blockIdx.x;     // key tile
    const int i0 = mt * 64;
    const int c0 = nt * 64;
    if (8 * c0 > i0 + 63) return;  // tile fully masked (causal on strided keys)

    __shared__ float As[64][36];   // 32 k-dims + pad (odd quad stride = 9)
    __shared__ float Bs[64][36];

    const int tid = threadIdx.x;
    const int tx = tid & 15;
    const int ty = tid >> 4;

    const float* qb = q + ((long)b * SS + i0) * DD;
    const float* kb = k + (long)b * SS * DD;

    float acc[4][4];
#pragma unroll
    for (int j = 0; j < 4; j++)
#pragma unroll
        for (int jj = 0; jj < 4; jj++) acc[j][jj] = 0.f;

    for (int kc = 0; kc < DD; kc += 32) {
        // cooperative load: 64 rows x 32 floats each for As and Bs
#pragma unroll
        for (int p = 0; p < 2; p++) {
            int idx = tid + 256 * p;
            int r  = idx >> 3;          // 0..63
            int cq = (idx & 7) * 4;     // 0..28
            float4 va = *reinterpret_cast<const float4*>(qb + (long)r * DD + kc + cq);
            *reinterpret_cast<float4*>(&As[r][cq]) = va;
            int key = c0 + r;           // < 512 always
            float4 vb = *reinterpret_cast<const float4*>(kb + (long)(KSTRIDE * key) * DD + kc + cq);
            *reinterpret_cast<float4*>(&Bs[r][cq]) = vb;
        }
        __syncthreads();

#pragma unroll
        for (int kq = 0; kq < 32; kq += 4) {
            float a[4][4], bb[4][4];
#pragma unroll
            for (int j = 0; j < 4; j++)
                *reinterpret_cast<float4*>(a[j]) =
                    *reinterpret_cast<const float4*>(&As[4 * ty + j][kq]);
#pragma unroll
            for (int jj = 0; jj < 4; jj++)
                *reinterpret_cast<float4*>(bb[jj]) =
                    *reinterpret_cast<const float4*>(&Bs[tx + 16 * jj][kq]);
#pragma unroll
            for (int j = 0; j < 4; j++)
#pragma unroll
                for (int jj = 0; jj < 4; jj++)
#pragma unroll
                    for (int kk = 0; kk < 4; kk++)
                        acc[j][jj] += a[j][kk] * bb[jj][kk];
        }
        __syncthreads();
    }

    // epilogue: exp + causal predicate, write unnormalized weights
#pragma unroll
    for (int j = 0; j < 4; j++) {
        int i = i0 + 4 * ty + j;
        float* wrow = g_w + ((long)b * SS + i) * NK;
#pragma unroll
        for (int jj = 0; jj < 4; jj++) {
            int c = c0 + tx + 16 * jj;
            float w = (KSTRIDE * c <= i) ? __expf(acc[j][jj] * SCALE) : 0.f;
            wrow[c] = w;
        }
    }
}

// ---------------------------------------------------------------------------
// Kernel 2: per-row sum of g_w -> g_rowsum; also scatter normalized weights
// into the strided attn_weights output (j = 8c positions).
// One warp per row; 8 rows per block.
// ---------------------------------------------------------------------------
__global__ __launch_bounds__(256) void rowsum_scatter_kernel(
    float* __restrict__ attn, int write_attn)
{
    const int row  = blockIdx.x * 8 + (threadIdx.x >> 5);  // 0..B*S-1
    const int lane = threadIdx.x & 31;

    const float* wr = g_w + (long)row * NK;
    float4 v[4];
    float s = 0.f;
#pragma unroll
    for (int qd = 0; qd < 4; qd++) {
        v[qd] = reinterpret_cast<const float4*>(wr)[lane + 32 * qd];
        s += v[qd].x + v[qd].y + v[qd].z + v[qd].w;
    }
#pragma unroll
    for (int o = 16; o >= 1; o >>= 1) s += __shfl_xor_sync(0xFFFFFFFFu, s, o);

    if (lane == 0) g_rowsum[row] = s;

    if (write_attn) {
        const float inv = 1.0f / s;         // always >0: c=0 valid for every row
        const int i = row & (SS - 1);
        float* arow = attn + (long)row * SS;
#pragma unroll
        for (int qd = 0; qd < 4; qd++) {
            int cbase = 4 * (lane + 32 * qd);
            float w4[4] = {v[qd].x, v[qd].y, v[qd].z, v[qd].w};
#pragma unroll
            for (int e = 0; e < 4; e++) {
                int j = KSTRIDE * (cbase + e);
                if (j <= i) arow[j] = w4[e] * inv;
            }
        }
    }
}

// ---------------------------------------------------------------------------
// Kernel 3: PV GEMM. out[b][i][d] = (1/rowsum[b*S+i]) * sum_c w[b][i][c]*v[b][8c][d]
// Tile: M=64 rows, N=64 d-cols, key-chunk=32.  Causal chunk skip.
// ---------------------------------------------------------------------------
__global__ __launch_bounds__(256) void pv_kernel(
    const float* __restrict__ v, float* __restrict__ out)
{
    const int b  = blockIdx.z;
    const int mt = blockIdx.y;   // row tile
    const int nt = blockIdx.x;   // d tile
    const int i0 = mt * 64;
    const int d0 = nt * 64;

    __shared__ float As[64][36];   // W rows x 32 keys (+pad)
    __shared__ float Bs[32][68];   // 32 keys x 64 d   (+pad, odd quad stride = 17)

    const int tid = threadIdx.x;
    const int tx = tid & 15;
    const int ty = tid >> 4;

    const float* wb = g_w + ((long)b * SS + i0) * NK;
    const float* vb = v + (long)b * SS * DD;

    float acc[4][4];
#pragma unroll
    for (int j = 0; j < 4; j++)
#pragma unroll
        for (int jj = 0; jj < 4; jj++) acc[j][jj] = 0.f;

    // number of 32-key chunks with any valid key for this row tile
    int nch = ((64 * mt + 63) >> 8) + 1;
    if (nch > 16) nch = 16;

    for (int ck = 0; ck < nch; ck++) {
        const int key0 = ck * 32;
        // load As: 64 rows x 32 keys
#pragma unroll
        for (int p = 0; p < 2; p++) {
            int idx = tid + 256 * p;
            int r  = idx >> 3;
            int cq = (idx & 7) * 4;
            float4 va = *reinterpret_cast<const float4*>(wb + (long)r * NK + key0 + cq);
            *reinterpret_cast<float4*>(&As[r][cq]) = va;
        }
        // load Bs: 32 key rows x 64 d
#pragma unroll
        for (int p = 0; p < 2; p++) {
            int idx = tid + 256 * p;
            int r  = idx >> 4;          // 0..31
            int c4 = (idx & 15) * 4;    // 0..60
            int key = key0 + r;         // < 512
            float4 vv = *reinterpret_cast<const float4*>(
                vb + (long)(KSTRIDE * key) * DD + d0 + c4);
            *reinterpret_cast<float4*>(&Bs[r][c4]) = vv;
        }
        __syncthreads();

#pragma unroll
        for (int cq = 0; cq < 32; cq += 4) {
            float a[4][4], bb[4][4];
#pragma unroll
            for (int j = 0; j < 4; j++)
                *reinterpret_cast<float4*>(a[j]) =
                    *reinterpret_cast<const float4*>(&As[4 * ty + j][cq]);
#pragma unroll
            for (int cc = 0; cc < 4; cc++)
                *reinterpret_cast<float4*>(bb[cc]) =
                    *reinterpret_cast<const float4*>(&Bs[cq + cc][4 * tx]);
#pragma unroll
            for (int j = 0; j < 4; j++)
#pragma unroll
                for (int cc = 0; cc < 4; cc++)
#pragma unroll
                    for (int jj = 0; jj < 4; jj++)
                        acc[j][jj] += a[j][cc] * bb[cc][jj];
        }
        __syncthreads();
    }

    // epilogue: normalize by rowsum, coalesced float4 store
#pragma unroll
    for (int j = 0; j < 4; j++) {
        int i = i0 + 4 * ty + j;
        float inv = 1.0f / g_rowsum[b * SS + i];
        float4 o;
        o.x = acc[j][0] * inv;
        o.y = acc[j][1] * inv;
        o.z = acc[j][2] * inv;
        o.w = acc[j][3] * inv;
        *reinterpret_cast<float4*>(out + ((long)b * SS + i) * DD + d0 + 4 * tx) = o;
    }
}

// ---------------------------------------------------------------------------
// Launch
// ---------------------------------------------------------------------------
extern "C" void kernel_launch(void* const* d_in, const int* in_sizes, int n_in,
                              void* d_out, int out_size)
{
    const float* q = (const float*)d_in[0];
    const float* k = (const float*)d_in[1];
    const float* v = (const float*)d_in[2];
    float* out = (float*)d_out;

    const long n_out  = (long)BB * SS * DD;       //  8,388,608
    const long n_attn = (long)BB * SS * SS;       // 67,108,864
    const long n_mask = (long)SS * SS;            // 16,777,216
    const long need = n_out + n_attn + n_mask;

    const int full = ((long)out_size >= need) ? 1 : 0;
    float* attn = out + n_out;
    float* mask = attn + n_attn;

    if (full) {
        init_out_kernel<<<4096, 256>>>(attn, mask);
    }

    qk_kernel<<<dim3(NK / 64, SS / 64, BB), 256>>>(q, k);

    rowsum_scatter_kernel<<<(BB * SS) / 8, 256>>>(attn, full);

    pv_kernel<<<dim3(DD / 64, SS / 64, BB), 256>>>(v, out);
}